// round 10
// baseline (speedup 1.0000x reference)
#include <cuda_runtime.h>
#include <cstdint>

#define SAMPLE 8192
#define KNN 8
#define WPB 4            // warps per block == queries per block
#define QPB 4
#define QUARTER (SAMPLE / 4)   // candidates per scanning warp
#define CAP 14           // survivor PAIR slots per (warp, query, lane)
#define SUB 512          // threshold subsample size
#define EPSV 1e-12f
#define SENT 0x7F800000FFFFFFFFull
#define FINF __int_as_float(0x7f800000)

// g_P: (x, y, z, |p|^2) query side.
// g_Q: (-2x, -2y, -2z, |p|^2) candidate side (phase-1 subsample reads).
// g_QP: pair-interleaved candidates, 2 float4 per pair:
//   [2p]   = (-2x_{2p}, -2x_{2p+1}, -2y_{2p}, -2y_{2p+1})
//   [2p+1] = (-2z_{2p}, -2z_{2p+1},  w_{2p},   w_{2p+1})
__device__ float4 g_P[SAMPLE];
__device__ float4 g_Q[SAMPLE];
__device__ float4 g_QP[SAMPLE];
__device__ float4 g_S[SAMPLE];

typedef unsigned long long ULL;

__device__ __forceinline__ ULL pk2(float lo, float hi) {
    ULL r;
    asm("mov.b64 %0, {%1, %2};" : "=l"(r) : "f"(lo), "f"(hi));
    return r;
}
__device__ __forceinline__ ULL add2(ULL a, ULL b) {
    ULL r;
    asm("add.rn.f32x2 %0, %1, %2;" : "=l"(r) : "l"(a), "l"(b));
    return r;
}
__device__ __forceinline__ ULL fma2(ULL a, ULL b, ULL c) {
    ULL r;
    asm("fma.rn.f32x2 %0, %1, %2, %3;" : "=l"(r) : "l"(a), "l"(b), "l"(c));
    return r;
}
__device__ __forceinline__ void upk2(ULL v, float& lo, float& hi) {
    asm("mov.b64 {%0, %1}, %2;" : "=f"(lo), "=f"(hi) : "l"(v));
}

__global__ void gather_kernel(const float* __restrict__ means,
                              const float* __restrict__ sh0,
                              const int* __restrict__ idx_raw,
                              float* __restrict__ out) {
    int i = blockIdx.x * blockDim.x + threadIdx.x;
    if (i == 0) *out = 0.f;
    if (i >= SAMPLE) return;
    // int64 vs int32 index detection: little-endian int64 < 2^31 has all odd
    // words zero.
    bool is64 = ((idx_raw[1] | idx_raw[3] | idx_raw[5] | idx_raw[7] |
                  idx_raw[9] | idx_raw[11] | idx_raw[13] | idx_raw[15]) == 0);
    long long j = is64 ? ((const long long*)idx_raw)[i] : (long long)idx_raw[i];
    float x = means[3 * j + 0];
    float y = means[3 * j + 1];
    float z = means[3 * j + 2];
    float sq = fmaf(z, z, fmaf(y, y, x * x));
    g_P[i] = make_float4(x, y, z, sq);
    g_Q[i] = make_float4(-2.f * x, -2.f * y, -2.f * z, sq);
    g_S[i] = make_float4(sh0[3 * j + 0], sh0[3 * j + 1], sh0[3 * j + 2], 0.f);
    float* qp = (float*)g_QP;
    int p = i >> 1, o = i & 1;
    qp[p * 8 + 0 + o] = -2.f * x;
    qp[p * 8 + 2 + o] = -2.f * y;
    qp[p * 8 + 4 + o] = -2.f * z;
    qp[p * 8 + 6 + o] = sq;
}

__device__ __forceinline__ void insert9(ULL heap[9], ULL key) {
    ULL cur = key;  // flat if-converted insert (cold paths only)
#pragma unroll
    for (int k = 0; k < 9; k++) {
        ULL h = heap[k];
        bool lt = cur < h;
        heap[k] = lt ? cur : h;
        cur = lt ? h : cur;
    }
}

// Block = 4 warps = 4 queries. Warp w scans candidate quarter w for ALL 4
// block queries (direct LDG, no tiles, no scan barriers), then owns the exact
// merge + loss for query w.
__global__ void __launch_bounds__(128) knn_loss_kernel(float* __restrict__ out) {
    __shared__ float Tsh[QPB];
    __shared__ unsigned short buf[WPB][QPB][CAP][32];  // survivor PAIR indices
    __shared__ unsigned char cnt[WPB][QPB][32];

    const int lane = threadIdx.x & 31;
    const int warp = threadIdx.x >> 5;
    const int qbase = blockIdx.x * QPB;

    // ---- Phase 1: this warp computes threshold T for query (qbase + warp).
    // Each lane keeps the min clamped d2 over its 16 subsample candidates;
    // 9 knockout rounds over the 32 lane minima yield the 9th-smallest of a
    // 512-subset, an upper bound on the full 9th-NN d2. Inflate by 1e-6 rel
    // to absorb packed-vs-scalar ulp skew in the scan.
    const float4 pw = g_P[qbase + warp];
    float mmin = FINF;
#pragma unroll 4
    for (int u = 0; u < SUB / 32; u++) {
        float4 c = g_Q[u * 32 + lane];
        float d = c.w + pw.w;
        d = fmaf(c.x, pw.x, d);
        d = fmaf(c.y, pw.y, d);
        d = fmaf(c.z, pw.z, d);
        mmin = fminf(mmin, fmaxf(d, EPSV));
    }
    {
        float m = mmin, T = FINF;
#pragma unroll
        for (int r = 0; r < 9; r++) {
            float t = m;
#pragma unroll
            for (int o = 16; o > 0; o >>= 1)
                t = fminf(t, __shfl_xor_sync(0xFFFFFFFFu, t, o));
            if (m == t) m = FINF;  // ties knock out together: T only loosens
            if (r == 8) T = t;
        }
        if (lane == 0) Tsh[warp] = T * 1.000001f;
        if (threadIdx.x < WPB * QPB * 32 / 128) {}  // no-op
    }
    __syncthreads();

    const float T0 = Tsh[0], T1 = Tsh[1], T2 = Tsh[2], T3 = Tsh[3];
    const float4 pi0 = g_P[qbase + 0];
    const float4 pi1 = g_P[qbase + 1];
    const float4 pi2 = g_P[qbase + 2];
    const float4 pi3 = g_P[qbase + 3];
    const ULL PX0 = pk2(pi0.x, pi0.x), PY0 = pk2(pi0.y, pi0.y);
    const ULL PZ0 = pk2(pi0.z, pi0.z), PW0 = pk2(pi0.w, pi0.w);
    const ULL PX1 = pk2(pi1.x, pi1.x), PY1 = pk2(pi1.y, pi1.y);
    const ULL PZ1 = pk2(pi1.z, pi1.z), PW1 = pk2(pi1.w, pi1.w);
    const ULL PX2 = pk2(pi2.x, pi2.x), PY2 = pk2(pi2.y, pi2.y);
    const ULL PZ2 = pk2(pi2.z, pi2.z), PW2 = pk2(pi2.w, pi2.w);
    const ULL PX3 = pk2(pi3.x, pi3.x), PY3 = pk2(pi3.y, pi3.y);
    const ULL PZ3 = pk2(pi3.z, pi3.z), PW3 = pk2(pi3.w, pi3.w);

    // ---- Phase 2: scan quarter `warp` for all 4 queries. Accept whole
    // PAIRS when min(d_a, d_b) <= T_q; fully predicated stores, no barriers.
    // Raw d2 <= clamped d2, so raw-vs-T never false-rejects.
    int c0 = 0, c1 = 0, c2 = 0, c3 = 0;
    const float4* base = g_QP + warp * (2 * (QUARTER / 2)) + 2 * lane;
    unsigned jp = warp * (QUARTER / 2) + lane;  // global pair index
#pragma unroll 4
    for (int it = 0; it < (QUARTER / 2) / 32; it++) {
        float4 A = base[0];
        float4 B = base[1];
        base += 64;
        ULL xv = pk2(A.x, A.y), yv = pk2(A.z, A.w);
        ULL zv = pk2(B.x, B.y), wv = pk2(B.z, B.w);
        ULL dq0 = fma2(zv, PZ0, fma2(yv, PY0, fma2(xv, PX0, add2(wv, PW0))));
        ULL dq1 = fma2(zv, PZ1, fma2(yv, PY1, fma2(xv, PX1, add2(wv, PW1))));
        ULL dq2 = fma2(zv, PZ2, fma2(yv, PY2, fma2(xv, PX2, add2(wv, PW2))));
        ULL dq3 = fma2(zv, PZ3, fma2(yv, PY3, fma2(xv, PX3, add2(wv, PW3))));
        float a, b;
        unsigned short jp16 = (unsigned short)jp;
        bool acc, st;
        upk2(dq0, a, b);
        acc = fminf(a, b) <= T0;
        st = acc & (c0 < CAP);
        if (st) buf[warp][0][c0][lane] = jp16;
        c0 += acc;
        upk2(dq1, a, b);
        acc = fminf(a, b) <= T1;
        st = acc & (c1 < CAP);
        if (st) buf[warp][1][c1][lane] = jp16;
        c1 += acc;
        upk2(dq2, a, b);
        acc = fminf(a, b) <= T2;
        st = acc & (c2 < CAP);
        if (st) buf[warp][2][c2][lane] = jp16;
        c2 += acc;
        upk2(dq3, a, b);
        acc = fminf(a, b) <= T3;
        st = acc & (c3 < CAP);
        if (st) buf[warp][3][c3][lane] = jp16;
        c3 += acc;
        jp += 32;
    }
    cnt[warp][0][lane] = (unsigned char)min(c0, CAP);
    cnt[warp][1][lane] = (unsigned char)min(c1, CAP);
    cnt[warp][2][lane] = (unsigned char)min(c2, CAP);
    cnt[warp][3][lane] = (unsigned char)min(c3, CAP);
    __syncthreads();

    // ---- Phase 3: this warp owns query q = warp. Gather survivors from all
    // 4 scanning warps, re-expand pairs, exact (d2, j)-keyed top-9.
    const int q = warp;
    const ULL QX = pk2(pw.x, pw.x), QY = pk2(pw.y, pw.y);
    const ULL QZ = pk2(pw.z, pw.z), QW = pk2(pw.w, pw.w);
    ULL heap[9];
#pragma unroll
    for (int k = 0; k < 9; k++) heap[k] = SENT;
#pragma unroll 1
    for (int wsrc = 0; wsrc < WPB; wsrc++) {
        int n = cnt[wsrc][q][lane];
        for (int s = 0; s < n; s++) {  // divergent, small (~1.4 avg)
            unsigned pidx = buf[wsrc][q][s][lane];
            float4 A = g_QP[2 * pidx];
            float4 B = g_QP[2 * pidx + 1];
            ULL xv = pk2(A.x, A.y), yv = pk2(A.z, A.w);
            ULL zv = pk2(B.x, B.y), wv = pk2(B.z, B.w);
            ULL dq = fma2(zv, QZ, fma2(yv, QY, fma2(xv, QX, add2(wv, QW))));
            float da, db;
            upk2(dq, da, db);
            unsigned j = 2 * pidx;
            insert9(heap, ((ULL)__float_as_uint(fmaxf(da, EPSV)) << 32) | j);
            insert9(heap,
                    ((ULL)__float_as_uint(fmaxf(db, EPSV)) << 32) | (j + 1));
        }
    }
    __syncwarp();

    // Warp pop-merge: >=9 real keys exist (the 9 knocked-out subsample
    // candidates all pass T and are buffered); real keys unique (distinct j)
    // -> exactly one lane pops per round.
    ULL mykey = SENT;
#pragma unroll
    for (int r = 0; r < 9; r++) {
        ULL cand = heap[0];
        ULL m = cand;
#pragma unroll
        for (int o = 16; o > 0; o >>= 1) {
            ULL other = __shfl_xor_sync(0xFFFFFFFFu, m, o);
            m = (other < m) ? other : m;
        }
        if (cand == m) {
#pragma unroll
            for (int k = 0; k < 8; k++) heap[k] = heap[k + 1];
            heap[8] = SENT;
        }
        if (lane == r) mykey = m;
    }

    // Ranks 1..8 (rank 0 = self/dup, dropped like knn_idx[:, 1:]). SENT is
    // harmless: d2=+inf -> weight 0; index masked in-bounds.
    float acc = 0.f;
    if (lane >= 1 && lane <= KNN) {
        int j = (int)(mykey & (unsigned)(SAMPLE - 1));
        float d2 = __uint_as_float((unsigned)(mykey >> 32));
        float w = __expf(-sqrtf(d2));
        float4 si = g_S[qbase + q];
        float4 sj = g_S[j];
        float dx = si.x - sj.x, dy = si.y - sj.y, dz = si.z - sj.z;
        acc = w * (dx * dx + dy * dy + dz * dz);
    }
#pragma unroll
    for (int o = 16; o > 0; o >>= 1)
        acc += __shfl_xor_sync(0xFFFFFFFFu, acc, o);
    if (lane == 0)
        atomicAdd(out, acc * (1.f / (float)(SAMPLE * KNN * 3)));
}

extern "C" void kernel_launch(void* const* d_in, const int* in_sizes, int n_in,
                              void* d_out, int out_size) {
    const float* means = (const float*)d_in[0];
    const float* sh0 = (const float*)d_in[1];
    const int* idx = (const int*)d_in[2];
    float* out = (float*)d_out;

    gather_kernel<<<SAMPLE / 256, 256>>>(means, sh0, idx, out);
    knn_loss_kernel<<<SAMPLE / QPB, 128>>>(out);
}

// round 11
// speedup vs baseline: 1.0037x; 1.0037x over previous
#include <cuda_runtime.h>
#include <cstdint>

#define SAMPLE 8192
#define KNN 8
#define WPB 4            // warps per block == queries per block
#define QPB 4
#define QUARTER (SAMPLE / 4)   // candidates per scanning warp
#define CAP 14           // survivor PAIR slots per (warp, query, lane)
#define SUB 512          // threshold subsample size
#define EPSV 1e-12f
#define SENT 0x7F800000FFFFFFFFull
#define FINF __int_as_float(0x7f800000)

// g_P: (x, y, z, |p|^2) query side.
// g_Q: (-2x, -2y, -2z, |p|^2) candidate side (phase-1 subsample reads).
// g_QP: pair-interleaved candidates, 2 float4 per pair:
//   [2p]   = (-2x_{2p}, -2x_{2p+1}, -2y_{2p}, -2y_{2p+1})
//   [2p+1] = (-2z_{2p}, -2z_{2p+1},  w_{2p},   w_{2p+1})
__device__ float4 g_P[SAMPLE];
__device__ float4 g_Q[SAMPLE];
__device__ float4 g_QP[SAMPLE];
__device__ float4 g_S[SAMPLE];

typedef unsigned long long ULL;

__device__ __forceinline__ ULL pk2(float lo, float hi) {
    ULL r;
    asm("mov.b64 %0, {%1, %2};" : "=l"(r) : "f"(lo), "f"(hi));
    return r;
}
__device__ __forceinline__ ULL add2(ULL a, ULL b) {
    ULL r;
    asm("add.rn.f32x2 %0, %1, %2;" : "=l"(r) : "l"(a), "l"(b));
    return r;
}
__device__ __forceinline__ ULL fma2(ULL a, ULL b, ULL c) {
    ULL r;
    asm("fma.rn.f32x2 %0, %1, %2, %3;" : "=l"(r) : "l"(a), "l"(b), "l"(c));
    return r;
}
__device__ __forceinline__ void upk2(ULL v, float& lo, float& hi) {
    asm("mov.b64 {%0, %1}, %2;" : "=f"(lo), "=f"(hi) : "l"(v));
}

__global__ void gather_kernel(const float* __restrict__ means,
                              const float* __restrict__ sh0,
                              const int* __restrict__ idx_raw,
                              float* __restrict__ out) {
    int i = blockIdx.x * blockDim.x + threadIdx.x;
    if (i == 0) *out = 0.f;
    if (i >= SAMPLE) return;
    // int64 vs int32 index detection: little-endian int64 < 2^31 has all odd
    // words zero.
    bool is64 = ((idx_raw[1] | idx_raw[3] | idx_raw[5] | idx_raw[7] |
                  idx_raw[9] | idx_raw[11] | idx_raw[13] | idx_raw[15]) == 0);
    long long j = is64 ? ((const long long*)idx_raw)[i] : (long long)idx_raw[i];
    float x = means[3 * j + 0];
    float y = means[3 * j + 1];
    float z = means[3 * j + 2];
    float sq = fmaf(z, z, fmaf(y, y, x * x));
    g_P[i] = make_float4(x, y, z, sq);
    g_Q[i] = make_float4(-2.f * x, -2.f * y, -2.f * z, sq);
    g_S[i] = make_float4(sh0[3 * j + 0], sh0[3 * j + 1], sh0[3 * j + 2], 0.f);
    float* qp = (float*)g_QP;
    int p = i >> 1, o = i & 1;
    qp[p * 8 + 0 + o] = -2.f * x;
    qp[p * 8 + 2 + o] = -2.f * y;
    qp[p * 8 + 4 + o] = -2.f * z;
    qp[p * 8 + 6 + o] = sq;
}

__device__ __forceinline__ void insert9(ULL heap[9], ULL key) {
    ULL cur = key;  // flat if-converted insert (cold paths only)
#pragma unroll
    for (int k = 0; k < 9; k++) {
        ULL h = heap[k];
        bool lt = cur < h;
        heap[k] = lt ? cur : h;
        cur = lt ? h : cur;
    }
}

// Block = 4 warps = 4 queries. Warp w scans candidate quarter w for ALL 4
// block queries (direct LDG, no tiles, no scan barriers), then owns the exact
// merge + loss for query w.
__global__ void __launch_bounds__(128) knn_loss_kernel(float* __restrict__ out) {
    __shared__ float Tsh[QPB];
    __shared__ unsigned short buf[WPB][QPB][CAP][32];  // survivor PAIR indices
    __shared__ unsigned char cnt[WPB][QPB][32];

    const int lane = threadIdx.x & 31;
    const int warp = threadIdx.x >> 5;
    const int qbase = blockIdx.x * QPB;

    // ---- Phase 1: this warp computes threshold T for query (qbase + warp).
    // Each lane keeps the min clamped d2 over its 16 subsample candidates;
    // 9 knockout rounds over the 32 lane minima yield the 9th-smallest of a
    // 512-subset, an upper bound on the full 9th-NN d2. Inflate by 1e-6 rel
    // to absorb packed-vs-scalar ulp skew in the scan.
    const float4 pw = g_P[qbase + warp];
    float mmin = FINF;
#pragma unroll 4
    for (int u = 0; u < SUB / 32; u++) {
        float4 c = g_Q[u * 32 + lane];
        float d = c.w + pw.w;
        d = fmaf(c.x, pw.x, d);
        d = fmaf(c.y, pw.y, d);
        d = fmaf(c.z, pw.z, d);
        mmin = fminf(mmin, fmaxf(d, EPSV));
    }
    {
        float m = mmin, T = FINF;
#pragma unroll
        for (int r = 0; r < 9; r++) {
            float t = m;
#pragma unroll
            for (int o = 16; o > 0; o >>= 1)
                t = fminf(t, __shfl_xor_sync(0xFFFFFFFFu, t, o));
            if (m == t) m = FINF;  // ties knock out together: T only loosens
            if (r == 8) T = t;
        }
        if (lane == 0) Tsh[warp] = T * 1.000001f;
        if (threadIdx.x < WPB * QPB * 32 / 128) {}  // no-op
    }
    __syncthreads();

    const float T0 = Tsh[0], T1 = Tsh[1], T2 = Tsh[2], T3 = Tsh[3];
    const float4 pi0 = g_P[qbase + 0];
    const float4 pi1 = g_P[qbase + 1];
    const float4 pi2 = g_P[qbase + 2];
    const float4 pi3 = g_P[qbase + 3];
    const ULL PX0 = pk2(pi0.x, pi0.x), PY0 = pk2(pi0.y, pi0.y);
    const ULL PZ0 = pk2(pi0.z, pi0.z), PW0 = pk2(pi0.w, pi0.w);
    const ULL PX1 = pk2(pi1.x, pi1.x), PY1 = pk2(pi1.y, pi1.y);
    const ULL PZ1 = pk2(pi1.z, pi1.z), PW1 = pk2(pi1.w, pi1.w);
    const ULL PX2 = pk2(pi2.x, pi2.x), PY2 = pk2(pi2.y, pi2.y);
    const ULL PZ2 = pk2(pi2.z, pi2.z), PW2 = pk2(pi2.w, pi2.w);
    const ULL PX3 = pk2(pi3.x, pi3.x), PY3 = pk2(pi3.y, pi3.y);
    const ULL PZ3 = pk2(pi3.z, pi3.z), PW3 = pk2(pi3.w, pi3.w);

    // ---- Phase 2: scan quarter `warp` for all 4 queries. Accept whole
    // PAIRS when min(d_a, d_b) <= T_q; fully predicated stores, no barriers.
    // Raw d2 <= clamped d2, so raw-vs-T never false-rejects.
    int c0 = 0, c1 = 0, c2 = 0, c3 = 0;
    const float4* base = g_QP + warp * (2 * (QUARTER / 2)) + 2 * lane;
    unsigned jp = warp * (QUARTER / 2) + lane;  // global pair index
#pragma unroll 4
    for (int it = 0; it < (QUARTER / 2) / 32; it++) {
        float4 A = base[0];
        float4 B = base[1];
        base += 64;
        ULL xv = pk2(A.x, A.y), yv = pk2(A.z, A.w);
        ULL zv = pk2(B.x, B.y), wv = pk2(B.z, B.w);
        ULL dq0 = fma2(zv, PZ0, fma2(yv, PY0, fma2(xv, PX0, add2(wv, PW0))));
        ULL dq1 = fma2(zv, PZ1, fma2(yv, PY1, fma2(xv, PX1, add2(wv, PW1))));
        ULL dq2 = fma2(zv, PZ2, fma2(yv, PY2, fma2(xv, PX2, add2(wv, PW2))));
        ULL dq3 = fma2(zv, PZ3, fma2(yv, PY3, fma2(xv, PX3, add2(wv, PW3))));
        float a, b;
        unsigned short jp16 = (unsigned short)jp;
        bool acc, st;
        upk2(dq0, a, b);
        acc = fminf(a, b) <= T0;
        st = acc & (c0 < CAP);
        if (st) buf[warp][0][c0][lane] = jp16;
        c0 += acc;
        upk2(dq1, a, b);
        acc = fminf(a, b) <= T1;
        st = acc & (c1 < CAP);
        if (st) buf[warp][1][c1][lane] = jp16;
        c1 += acc;
        upk2(dq2, a, b);
        acc = fminf(a, b) <= T2;
        st = acc & (c2 < CAP);
        if (st) buf[warp][2][c2][lane] = jp16;
        c2 += acc;
        upk2(dq3, a, b);
        acc = fminf(a, b) <= T3;
        st = acc & (c3 < CAP);
        if (st) buf[warp][3][c3][lane] = jp16;
        c3 += acc;
        jp += 32;
    }
    cnt[warp][0][lane] = (unsigned char)min(c0, CAP);
    cnt[warp][1][lane] = (unsigned char)min(c1, CAP);
    cnt[warp][2][lane] = (unsigned char)min(c2, CAP);
    cnt[warp][3][lane] = (unsigned char)min(c3, CAP);
    __syncthreads();

    // ---- Phase 3: this warp owns query q = warp. Gather survivors from all
    // 4 scanning warps, re-expand pairs, exact (d2, j)-keyed top-9.
    const int q = warp;
    const ULL QX = pk2(pw.x, pw.x), QY = pk2(pw.y, pw.y);
    const ULL QZ = pk2(pw.z, pw.z), QW = pk2(pw.w, pw.w);
    ULL heap[9];
#pragma unroll
    for (int k = 0; k < 9; k++) heap[k] = SENT;
#pragma unroll 1
    for (int wsrc = 0; wsrc < WPB; wsrc++) {
        int n = cnt[wsrc][q][lane];
        for (int s = 0; s < n; s++) {  // divergent, small (~1.4 avg)
            unsigned pidx = buf[wsrc][q][s][lane];
            float4 A = g_QP[2 * pidx];
            float4 B = g_QP[2 * pidx + 1];
            ULL xv = pk2(A.x, A.y), yv = pk2(A.z, A.w);
            ULL zv = pk2(B.x, B.y), wv = pk2(B.z, B.w);
            ULL dq = fma2(zv, QZ, fma2(yv, QY, fma2(xv, QX, add2(wv, QW))));
            float da, db;
            upk2(dq, da, db);
            unsigned j = 2 * pidx;
            insert9(heap, ((ULL)__float_as_uint(fmaxf(da, EPSV)) << 32) | j);
            insert9(heap,
                    ((ULL)__float_as_uint(fmaxf(db, EPSV)) << 32) | (j + 1));
        }
    }
    __syncwarp();

    // Warp pop-merge: >=9 real keys exist (the 9 knocked-out subsample
    // candidates all pass T and are buffered); real keys unique (distinct j)
    // -> exactly one lane pops per round.
    ULL mykey = SENT;
#pragma unroll
    for (int r = 0; r < 9; r++) {
        ULL cand = heap[0];
        ULL m = cand;
#pragma unroll
        for (int o = 16; o > 0; o >>= 1) {
            ULL other = __shfl_xor_sync(0xFFFFFFFFu, m, o);
            m = (other < m) ? other : m;
        }
        if (cand == m) {
#pragma unroll
            for (int k = 0; k < 8; k++) heap[k] = heap[k + 1];
            heap[8] = SENT;
        }
        if (lane == r) mykey = m;
    }

    // Ranks 1..8 (rank 0 = self/dup, dropped like knn_idx[:, 1:]). SENT is
    // harmless: d2=+inf -> weight 0; index masked in-bounds.
    float acc = 0.f;
    if (lane >= 1 && lane <= KNN) {
        int j = (int)(mykey & (unsigned)(SAMPLE - 1));
        float d2 = __uint_as_float((unsigned)(mykey >> 32));
        float w = __expf(-sqrtf(d2));
        float4 si = g_S[qbase + q];
        float4 sj = g_S[j];
        float dx = si.x - sj.x, dy = si.y - sj.y, dz = si.z - sj.z;
        acc = w * (dx * dx + dy * dy + dz * dz);
    }
#pragma unroll
    for (int o = 16; o > 0; o >>= 1)
        acc += __shfl_xor_sync(0xFFFFFFFFu, acc, o);
    if (lane == 0)
        atomicAdd(out, acc * (1.f / (float)(SAMPLE * KNN * 3)));
}

extern "C" void kernel_launch(void* const* d_in, const int* in_sizes, int n_in,
                              void* d_out, int out_size) {
    const float* means = (const float*)d_in[0];
    const float* sh0 = (const float*)d_in[1];
    const int* idx = (const int*)d_in[2];
    float* out = (float*)d_out;

    gather_kernel<<<SAMPLE / 256, 256>>>(means, sh0, idx, out);
    knn_loss_kernel<<<SAMPLE / QPB, 128>>>(out);
}

// round 12
// speedup vs baseline: 1.0127x; 1.0090x over previous
#include <cuda_runtime.h>
#include <cstdint>

#define SAMPLE 8192
#define KNN 8
#define WPB 8            // query-warps per block
#define CAP 24           // survivor slots per (warp, lane)
#define SUB 512          // threshold subsample size
#define NB 512           // x-buckets
#define EPSV 1e-12f
#define SENT 0x7F800000FFFFFFFFull
#define FINF __int_as_float(0x7f800000)

// g_P: (x, y, z, |p|^2) per gathered point (query & candidate identity).
// g_S: sh0 per gathered point.
// g_C: x-bucket-sorted candidates in Q-form (-2x, -2y, -2z, |p|^2).
// g_CI: original gathered index of each sorted slot.
// g_boff: bucket start offsets (NB+1).
__device__ float4 g_P[SAMPLE];
__device__ float4 g_S[SAMPLE];
__device__ float4 g_C[SAMPLE];
__device__ unsigned short g_CI[SAMPLE];
__device__ unsigned g_boff[NB + 1];

__device__ __forceinline__ int bucket_of(float x) {
    int b = (int)((x + 8.f) * (NB / 16.f));  // trunc == floor for x > -8
    return min(NB - 1, max(0, b));
}

__global__ void gather_kernel(const float* __restrict__ means,
                              const float* __restrict__ sh0,
                              const int* __restrict__ idx_raw,
                              float* __restrict__ out) {
    int i = blockIdx.x * blockDim.x + threadIdx.x;
    if (i == 0) *out = 0.f;
    if (i >= SAMPLE) return;
    // int64 vs int32 index detection: little-endian int64 < 2^31 has all odd
    // words zero.
    bool is64 = ((idx_raw[1] | idx_raw[3] | idx_raw[5] | idx_raw[7] |
                  idx_raw[9] | idx_raw[11] | idx_raw[13] | idx_raw[15]) == 0);
    long long j = is64 ? ((const long long*)idx_raw)[i] : (long long)idx_raw[i];
    float x = means[3 * j + 0];
    float y = means[3 * j + 1];
    float z = means[3 * j + 2];
    float sq = fmaf(z, z, fmaf(y, y, x * x));
    g_P[i] = make_float4(x, y, z, sq);
    g_S[i] = make_float4(sh0[3 * j + 0], sh0[3 * j + 1], sh0[3 * j + 2], 0.f);
}

// Single block: count -> prefix-scan -> scatter into x-bucket order.
__global__ void __launch_bounds__(1024) prep_kernel() {
    __shared__ unsigned bcnt[NB];
    __shared__ unsigned cur[NB];
    __shared__ unsigned wsum[NB / 32];
    const int tid = threadIdx.x;
    const int lane = tid & 31;

    if (tid < NB) bcnt[tid] = 0;
    __syncthreads();
    for (int i = tid; i < SAMPLE; i += 1024)
        atomicAdd(&bcnt[bucket_of(g_P[i].x)], 1u);
    __syncthreads();

    // Exclusive prefix scan over NB=512 counts (warps 0..15 fully active).
    unsigned v = 0, x = 0;
    if (tid < NB) {
        v = bcnt[tid];
        x = v;
#pragma unroll
        for (int o = 1; o < 32; o <<= 1) {
            unsigned y = __shfl_up_sync(0xFFFFFFFFu, x, o);
            if (lane >= o) x += y;
        }
        if (lane == 31) wsum[tid >> 5] = x;
    }
    __syncthreads();
    if (tid < NB / 32) {
        unsigned w = wsum[tid], s = w;
#pragma unroll
        for (int o = 1; o < NB / 32; o <<= 1) {
            unsigned y = __shfl_up_sync(0xFFFFu, s, o);
            if (tid >= o) s += y;
        }
        wsum[tid] = s - w;  // exclusive
    }
    __syncthreads();
    if (tid < NB) {
        unsigned off = x - v + wsum[tid >> 5];
        g_boff[tid] = off;
        cur[tid] = off;
    }
    if (tid == 0) g_boff[NB] = SAMPLE;
    __syncthreads();

    for (int i = tid; i < SAMPLE; i += 1024) {
        float4 p = g_P[i];
        unsigned pos = atomicAdd(&cur[bucket_of(p.x)], 1u);
        g_C[pos] = make_float4(-2.f * p.x, -2.f * p.y, -2.f * p.z, p.w);
        g_CI[pos] = (unsigned short)i;
    }
}

__device__ __forceinline__ void insert9(unsigned long long heap[9],
                                        unsigned long long key) {
    unsigned long long cur = key;  // flat if-converted insert (cold path)
#pragma unroll
    for (int k = 0; k < 9; k++) {
        unsigned long long h = heap[k];
        bool lt = cur < h;
        heap[k] = lt ? cur : h;
        cur = lt ? h : cur;
    }
}

// One warp per query; scans only the x-window of the sorted candidate array.
__global__ void __launch_bounds__(32 * WPB) knn_loss_kernel(
    float* __restrict__ out) {
    __shared__ unsigned short buf[WPB][CAP][32];

    const int lane = threadIdx.x & 31;
    const int warp = threadIdx.x >> 5;
    const int i = blockIdx.x * WPB + warp;
    const float4 pi = g_P[i];

    // ---- Phase 1: T = 9th-smallest clamped d2 over a strided 512-subsample
    // of the sorted array (a subset, so its 9th order stat >= the true 9th-NN
    // d2). Per-lane min + 9 knockout rounds; ties knock out together, which
    // only loosens T (still valid).
    float mmin = FINF;
#pragma unroll
    for (int u = 0; u < SUB / 32; u++) {
        float4 c = g_C[(u * 32 + lane) * (SAMPLE / SUB)];
        float d = c.w + pi.w;
        d = fmaf(c.x, pi.x, d);
        d = fmaf(c.y, pi.y, d);
        d = fmaf(c.z, pi.z, d);
        mmin = fminf(mmin, fmaxf(d, EPSV));
    }
    float T = FINF;
    {
        float m = mmin;
#pragma unroll
        for (int r = 0; r < 9; r++) {
            float t = m;
#pragma unroll
            for (int o = 16; o > 0; o >>= 1)
                t = fminf(t, __shfl_xor_sync(0xFFFFFFFFu, t, o));
            if (m == t) m = FINF;
            if (r == 8) T = t;
        }
    }

    // ---- Window: any candidate with (x_j - x_i)^2 > T has d2 > T and cannot
    // be in the top-9 (>=9 candidates have d2 <= T). Whole-bucket inclusion
    // plus an ulp guard on sqrt makes pruning strictly conservative.
    const float s = sqrtf(T) * 1.0000024f;
    const int blo = bucket_of(pi.x - s);
    const int bhi = bucket_of(pi.x + s);
    const unsigned lo = g_boff[blo];
    const unsigned hi = g_boff[bhi + 1];

    // ---- Phase 2: scan the window; predicated lane-private survivor stores.
    int cnt = 0;
    for (unsigned p = lo + lane; p < hi; p += 32) {
        float4 c = g_C[p];
        float d = c.w + pi.w;
        d = fmaf(c.x, pi.x, d);
        d = fmaf(c.y, pi.y, d);
        d = fmaf(c.z, pi.z, d);
        bool a = d <= T;  // raw <= clamped: never false-rejects
        bool st = a & (cnt < CAP);
        if (st) buf[warp][cnt][lane] = (unsigned short)p;
        cnt += a;
    }

    // ---- Phase 3: exact (d2, orig_j)-keyed top-9 over survivors.
    unsigned long long heap[9];
#pragma unroll
    for (int k = 0; k < 9; k++) heap[k] = SENT;
    int n = min(cnt, CAP);
    for (int ss = 0; ss < n; ss++) {
        unsigned p = buf[warp][ss][lane];
        float4 c = g_C[p];
        float d = c.w + pi.w;
        d = fmaf(c.x, pi.x, d);
        d = fmaf(c.y, pi.y, d);
        d = fmaf(c.z, pi.z, d);
        float d2c = fmaxf(d, EPSV);
        unsigned j = g_CI[p];
        insert9(heap, ((unsigned long long)__float_as_uint(d2c) << 32) | j);
    }
    __syncwarp();

    // Warp pop-merge; real keys unique (distinct orig j). Sentinel pops (only
    // possible under CAP overflow) contribute weight exp(-inf)=0.
    unsigned long long mykey = SENT;
#pragma unroll
    for (int r = 0; r < 9; r++) {
        unsigned long long cand = heap[0];
        unsigned long long m = cand;
#pragma unroll
        for (int o = 16; o > 0; o >>= 1) {
            unsigned long long other = __shfl_xor_sync(0xFFFFFFFFu, m, o);
            m = (other < m) ? other : m;
        }
        if (cand == m) {
#pragma unroll
            for (int k = 0; k < 8; k++) heap[k] = heap[k + 1];
            heap[8] = SENT;
        }
        if (lane == r) mykey = m;
    }

    // Ranks 1..8 (rank 0 = self/dup, dropped like knn_idx[:, 1:]).
    float acc = 0.f;
    if (lane >= 1 && lane <= KNN) {
        int j = (int)(mykey & (unsigned)(SAMPLE - 1));
        float d2 = __uint_as_float((unsigned)(mykey >> 32));
        float w = __expf(-sqrtf(d2));
        float4 si = g_S[i];
        float4 sj = g_S[j];
        float dx = si.x - sj.x, dy = si.y - sj.y, dz = si.z - sj.z;
        acc = w * (dx * dx + dy * dy + dz * dz);
    }
#pragma unroll
    for (int o = 16; o > 0; o >>= 1)
        acc += __shfl_xor_sync(0xFFFFFFFFu, acc, o);
    if (lane == 0)
        atomicAdd(out, acc * (1.f / (float)(SAMPLE * KNN * 3)));
}

extern "C" void kernel_launch(void* const* d_in, const int* in_sizes, int n_in,
                              void* d_out, int out_size) {
    const float* means = (const float*)d_in[0];
    const float* sh0 = (const float*)d_in[1];
    const int* idx = (const int*)d_in[2];
    float* out = (float*)d_out;

    gather_kernel<<<SAMPLE / 256, 256>>>(means, sh0, idx, out);
    prep_kernel<<<1, 1024>>>();
    knn_loss_kernel<<<SAMPLE / WPB, 32 * WPB>>>(out);
}

// round 13
// speedup vs baseline: 1.8125x; 1.7897x over previous
#include <cuda_runtime.h>
#include <cstdint>

#define SAMPLE 8192
#define KNN 8
#define WPB 8            // query-warps per block
#define CAP 16           // survivor slots per (warp, lane)
#define SUB 512          // threshold subsample size (x-local, contiguous)
#define NB 512           // x-buckets over [-4, 4]
#define EPSV 1e-12f
#define SENT 0x7F800000FFFFFFFFull
#define FINF __int_as_float(0x7f800000)

// g_P: (x, y, z, |p|^2) per gathered point.  g_S: gathered sh0.
// g_C: x-bucket-sorted candidates in Q-form (-2x, -2y, -2z, |p|^2).
// g_CI: original gathered index per sorted slot.  g_boff: bucket offsets.
__device__ float4 g_P[SAMPLE];
__device__ float4 g_S[SAMPLE];
__device__ float4 g_C[SAMPLE];
__device__ unsigned short g_CI[SAMPLE];
__device__ unsigned g_boff[NB + 1];
__device__ unsigned g_bcnt[NB];
__device__ unsigned g_cur[NB];

// Clamped bucketing is monotone non-decreasing in x, which is all the window
// logic needs (points sorted by bucket; window = contiguous bucket span).
__device__ __forceinline__ int bucket_of(float x) {
    int b = (int)((x + 4.f) * (NB / 8.f));
    return min(NB - 1, max(0, b));
}

__global__ void init_kernel(float* __restrict__ out) {
    if (threadIdx.x == 0) *out = 0.f;
    g_bcnt[threadIdx.x] = 0;
}

__global__ void gather_kernel(const float* __restrict__ means,
                              const float* __restrict__ sh0,
                              const int* __restrict__ idx_raw) {
    int i = blockIdx.x * blockDim.x + threadIdx.x;
    if (i >= SAMPLE) return;
    // int64 vs int32 index detection: little-endian int64 < 2^31 has all odd
    // words zero.
    bool is64 = ((idx_raw[1] | idx_raw[3] | idx_raw[5] | idx_raw[7] |
                  idx_raw[9] | idx_raw[11] | idx_raw[13] | idx_raw[15]) == 0);
    long long j = is64 ? ((const long long*)idx_raw)[i] : (long long)idx_raw[i];
    float x = means[3 * j + 0];
    float y = means[3 * j + 1];
    float z = means[3 * j + 2];
    float sq = fmaf(z, z, fmaf(y, y, x * x));
    g_P[i] = make_float4(x, y, z, sq);
    g_S[i] = make_float4(sh0[3 * j + 0], sh0[3 * j + 1], sh0[3 * j + 2], 0.f);
    atomicAdd(&g_bcnt[bucket_of(x)], 1u);
}

// One block: exclusive prefix scan of the NB=512 bucket counts.
__global__ void __launch_bounds__(NB) scan_kernel() {
    __shared__ unsigned wsum[NB / 32];
    const int tid = threadIdx.x;
    const int lane = tid & 31;
    unsigned v = g_bcnt[tid];
    unsigned x = v;
#pragma unroll
    for (int o = 1; o < 32; o <<= 1) {
        unsigned y = __shfl_up_sync(0xFFFFFFFFu, x, o);
        if (lane >= o) x += y;
    }
    if (lane == 31) wsum[tid >> 5] = x;
    __syncthreads();
    if (tid < NB / 32) {
        unsigned w = wsum[tid], s = w;
#pragma unroll
        for (int o = 1; o < NB / 32; o <<= 1) {
            unsigned y = __shfl_up_sync(0xFFFFu, s, o);
            if (tid >= o) s += y;
        }
        wsum[tid] = s - w;  // exclusive across warps
    }
    __syncthreads();
    unsigned off = x - v + wsum[tid >> 5];
    g_boff[tid] = off;
    g_cur[tid] = off;
    if (tid == 0) g_boff[NB] = SAMPLE;
}

__global__ void scatter_kernel() {
    int i = blockIdx.x * blockDim.x + threadIdx.x;
    if (i >= SAMPLE) return;
    float4 p = g_P[i];
    unsigned pos = atomicAdd(&g_cur[bucket_of(p.x)], 1u);
    g_C[pos] = make_float4(-2.f * p.x, -2.f * p.y, -2.f * p.z, p.w);
    g_CI[pos] = (unsigned short)i;
}

__device__ __forceinline__ void insert9(unsigned long long heap[9],
                                        unsigned long long key) {
    unsigned long long cur = key;  // flat if-converted insert (cold path)
#pragma unroll
    for (int k = 0; k < 9; k++) {
        unsigned long long h = heap[k];
        bool lt = cur < h;
        heap[k] = lt ? cur : h;
        cur = lt ? h : cur;
    }
}

// One warp per query; scans only the x-window of the sorted candidate array.
__global__ void __launch_bounds__(32 * WPB) knn_loss_kernel(
    float* __restrict__ out) {
    __shared__ unsigned short buf[WPB][CAP][32];

    const int lane = threadIdx.x & 31;
    const int warp = threadIdx.x >> 5;
    const int i = blockIdx.x * WPB + warp;
    const float4 pi = g_P[i];

    // ---- Phase 1: T = 9th-smallest clamped d2 over the 512 sorted
    // candidates x-nearest to the query (contiguous slice centered on the
    // query's bucket offset). Any subset's 9th order stat >= the true 9th-NN
    // d2, and x-local subsets make T nearly tight. Per-lane min + 9 knockout
    // rounds; ties knock out together (T only loosens, stays valid).
    int start = (int)g_boff[bucket_of(pi.x)] - SUB / 2;
    start = min(SAMPLE - SUB, max(0, start));
    float mmin = FINF;
#pragma unroll
    for (int u = 0; u < SUB / 32; u++) {
        float4 c = g_C[start + u * 32 + lane];
        float d = c.w + pi.w;
        d = fmaf(c.x, pi.x, d);
        d = fmaf(c.y, pi.y, d);
        d = fmaf(c.z, pi.z, d);
        mmin = fminf(mmin, fmaxf(d, EPSV));
    }
    float T = FINF;
    {
        float m = mmin;
#pragma unroll
        for (int r = 0; r < 9; r++) {
            float t = m;
#pragma unroll
            for (int o = 16; o > 0; o >>= 1)
                t = fminf(t, __shfl_xor_sync(0xFFFFFFFFu, t, o));
            if (m == t) m = FINF;
            if (r == 8) T = t;
        }
    }

    // ---- Window: if (x_j - x_i)^2 > T then d2 > T, and >=9 candidates have
    // d2c <= T, so such j can never enter the top-9. Whole-bucket inclusion
    // plus an ulp guard keeps pruning strictly conservative.
    const float s = sqrtf(T) * 1.0000024f;
    const unsigned lo = g_boff[bucket_of(pi.x - s)];
    const unsigned hi = g_boff[bucket_of(pi.x + s) + 1];

    // ---- Phase 2: scan the window; predicated lane-private survivor stores.
    int cnt = 0;
    for (unsigned p = lo + lane; p < hi; p += 32) {
        float4 c = g_C[p];
        float d = c.w + pi.w;
        d = fmaf(c.x, pi.x, d);
        d = fmaf(c.y, pi.y, d);
        d = fmaf(c.z, pi.z, d);
        bool a = d <= T;  // raw <= clamped: never false-rejects
        bool st = a & (cnt < CAP);
        if (st) buf[warp][cnt][lane] = (unsigned short)p;
        cnt += a;
    }

    // ---- Phase 3: exact (d2, orig_j)-keyed top-9 over survivors.
    unsigned long long heap[9];
#pragma unroll
    for (int k = 0; k < 9; k++) heap[k] = SENT;
    int n = min(cnt, CAP);
    for (int ss = 0; ss < n; ss++) {
        unsigned p = buf[warp][ss][lane];
        float4 c = g_C[p];
        float d = c.w + pi.w;
        d = fmaf(c.x, pi.x, d);
        d = fmaf(c.y, pi.y, d);
        d = fmaf(c.z, pi.z, d);
        float d2c = fmaxf(d, EPSV);
        unsigned j = g_CI[p];
        insert9(heap, ((unsigned long long)__float_as_uint(d2c) << 32) | j);
    }
    __syncwarp();

    // Warp pop-merge; real keys unique (distinct orig j) -> one pop/round.
    unsigned long long mykey = SENT;
#pragma unroll
    for (int r = 0; r < 9; r++) {
        unsigned long long cand = heap[0];
        unsigned long long m = cand;
#pragma unroll
        for (int o = 16; o > 0; o >>= 1) {
            unsigned long long other = __shfl_xor_sync(0xFFFFFFFFu, m, o);
            m = (other < m) ? other : m;
        }
        if (cand == m) {
#pragma unroll
            for (int k = 0; k < 8; k++) heap[k] = heap[k + 1];
            heap[8] = SENT;
        }
        if (lane == r) mykey = m;
    }

    // Ranks 1..8 (rank 0 = self/dup, dropped like knn_idx[:, 1:]).
    float acc = 0.f;
    if (lane >= 1 && lane <= KNN) {
        int j = (int)(mykey & (unsigned)(SAMPLE - 1));
        float d2 = __uint_as_float((unsigned)(mykey >> 32));
        float w = __expf(-sqrtf(d2));
        float4 si = g_S[i];
        float4 sj = g_S[j];
        float dx = si.x - sj.x, dy = si.y - sj.y, dz = si.z - sj.z;
        acc = w * (dx * dx + dy * dy + dz * dz);
    }
#pragma unroll
    for (int o = 16; o > 0; o >>= 1)
        acc += __shfl_xor_sync(0xFFFFFFFFu, acc, o);
    if (lane == 0)
        atomicAdd(out, acc * (1.f / (float)(SAMPLE * KNN * 3)));
}

extern "C" void kernel_launch(void* const* d_in, const int* in_sizes, int n_in,
                              void* d_out, int out_size) {
    const float* means = (const float*)d_in[0];
    const float* sh0 = (const float*)d_in[1];
    const int* idx = (const int*)d_in[2];
    float* out = (float*)d_out;

    init_kernel<<<1, NB>>>(out);
    gather_kernel<<<SAMPLE / 256, 256>>>(means, sh0, idx);
    scan_kernel<<<1, NB>>>();
    scatter_kernel<<<SAMPLE / 256, 256>>>();
    knn_loss_kernel<<<SAMPLE / WPB, 32 * WPB>>>(out);
}